// round 14
// baseline (speedup 1.0000x reference)
#include <cuda_runtime.h>
#include <cstdint>
#include <math_constants.h>

// ---------------------------------------------------------------------------
// MDescAug: per-query candidate reranking with descriptor augmentation.
//   X: [50000,512] f32,  Q: [100,512] f32,  ranks: [50000,100] i32/i64 (probed)
// Output f32 concat: rerank_final[100,400], res_top[100,400], pre[100,400],
//                    x_dba[100,400,512]
// Strategy: 1-term bf16 tensor GEMM -> approx S (selection only); standalone
// high-occupancy approx top-16 select; exact kernel with 4-warp-parallel
// serial-fp32 chains (bitwise reference S entries) + fused epilogue.
// ---------------------------------------------------------------------------

#define NDB  50000
#define NQ   100
#define DIM  512
#define MM   400
#define MPAD 448              // 7 * 64, zero-padded rows
#define KTOP 10
#define NCAND 16
#define BETA 0.15f

#define OFF_RERANK 0
#define OFF_RESTOP 40000
#define OFF_PRE    80000
#define OFF_XDBA   120000
#define FULL_OUT   20600000

// Scratch (device globals; no allocation allowed)
__device__ float g_Xs[(size_t)NQ * MPAD * DIM];   // gathered (padded)
__device__ float g_S[(size_t)NQ * MM * MM];       // approx similarity
__device__ int   g_rt[NQ * MM];
__device__ int   g_cand[NQ * MM * NCAND];
__device__ float g_restop[NQ * MM];
__device__ int   g_is64;

// ---- order-preserving float<->uint ------------------------------------------
__device__ __forceinline__ unsigned int ordf(float f) {
    unsigned int u = __float_as_uint(f);
    return (u & 0x80000000u) ? ~u : (u | 0x80000000u);
}
__device__ __forceinline__ float unordf(unsigned int o) {
    return __uint_as_float((o & 0x80000000u) ? (o & 0x7FFFFFFFu) : ~o);
}
__device__ __forceinline__ unsigned long long pack_key(float v, int idx) {
    return ((unsigned long long)ordf(v) << 32) |
           (unsigned long long)(0xFFFFFFFFu - (unsigned int)idx);
}

// ---- probe: int64 vs int32 ranks --------------------------------------------
__global__ void probe_kernel(const int* __restrict__ r) {
    __shared__ int cnt;
    if (threadIdx.x == 0) cnt = 0;
    __syncthreads();
    int nz = 0;
    for (int i = threadIdx.x; i < 1024; i += blockDim.x)
        nz += (r[2 * i + 1] != 0);
    atomicAdd(&cnt, nz);
    __syncthreads();
    if (threadIdx.x == 0) g_is64 = (cnt < 100) ? 1 : 0;
}

// ---- gather Xs[q][m][:] = X[ranks[m][q]][:]; zero-pad rows 400..447 ---------
__global__ __launch_bounds__(128) void gather_kernel(const float* __restrict__ X,
                                                     const void* __restrict__ ranks) {
    int m = blockIdx.x, q = blockIdx.y, tid = threadIdx.x;
    float4* dst = (float4*)(g_Xs + ((size_t)q * MPAD + m) * DIM);
    if (m >= MM) {
        dst[tid] = make_float4(0.f, 0.f, 0.f, 0.f);
        return;
    }
    int rid;
    if (g_is64) rid = (int)((const long long*)ranks)[(size_t)m * NQ + q];
    else        rid = ((const int*)ranks)[(size_t)m * NQ + q];
    if (tid == 0) g_rt[q * MM + m] = rid;
    const float4* src = (const float4*)(X + (size_t)rid * DIM);
    dst[tid] = src[tid];
}

// ---- bf16 pack: (x0, x1) -> bf16x2 ------------------------------------------
__device__ __forceinline__ unsigned cvt_bf2(float x0, float x1) {
    unsigned h;
    asm("cvt.rn.bf16x2.f32 %0, %1, %2;" : "=r"(h) : "f"(x1), "f"(x0));
    return h;
}

__device__ __forceinline__ void mma_bf16(float* c, const unsigned* a, const unsigned* b) {
    asm volatile(
        "mma.sync.aligned.m16n8k16.row.col.f32.bf16.bf16.f32 "
        "{%0,%1,%2,%3}, {%4,%5,%6,%7}, {%8,%9}, {%0,%1,%2,%3};\n"
        : "+f"(c[0]), "+f"(c[1]), "+f"(c[2]), "+f"(c[3])
        : "r"(a[0]), "r"(a[1]), "r"(a[2]), "r"(a[3]), "r"(b[0]), "r"(b[1]));
}

// ---- batched symmetric approx GEMM, plain bf16 ------------------------------
// Block tile 64x64, BK=32, 128 threads (4 warps, 2x2 of 32x32 warp tiles).
#define LDW 18   // smem row stride in 32-bit words (36 halves); conflict-free
__global__ __launch_bounds__(128) void gemm_kernel() {
    __shared__ unsigned Ah[64 * LDW];
    __shared__ unsigned Bh[64 * LDW];

    int p = blockIdx.x, q = blockIdx.y;
    int bi = 0, bj = 0;
    {
        int t = 0;
        #pragma unroll
        for (int i = 0; i < 7; i++) {
            int c = 7 - i;
            if (p < t + c) { bi = i; bj = i + (p - t); break; }
            t += c;
        }
    }
    const float* Xq = g_Xs + (size_t)q * MPAD * DIM;
    const float* Ap = Xq + (size_t)bi * 64 * DIM;
    const float* Bp = Xq + (size_t)bj * 64 * DIM;

    int tid = threadIdx.x;
    int warp = tid >> 5, lane = tid & 31;
    int wm = warp >> 1, wn = warp & 1;
    int lr = lane >> 2, lc = lane & 3;

    int r0s = tid >> 3, c0s = tid & 7;

    float acc[2][4][4];
    #pragma unroll
    for (int mi = 0; mi < 2; mi++)
        #pragma unroll
        for (int ni = 0; ni < 4; ni++)
            #pragma unroll
            for (int e = 0; e < 4; e++) acc[mi][ni][e] = 0.0f;

    float4 pA[4], pB[4];
    #pragma unroll
    for (int i = 0; i < 4; i++) {
        pA[i] = *(const float4*)(Ap + (size_t)(i * 16 + r0s) * DIM + c0s * 4);
        pB[i] = *(const float4*)(Bp + (size_t)(i * 16 + r0s) * DIM + c0s * 4);
    }

    for (int ch = 0; ch < 16; ch++) {
        __syncthreads();
        #pragma unroll
        for (int i = 0; i < 4; i++) {
            int w = (i * 16 + r0s) * LDW + 2 * c0s;
            Ah[w]     = cvt_bf2(pA[i].x, pA[i].y);
            Ah[w + 1] = cvt_bf2(pA[i].z, pA[i].w);
            Bh[w]     = cvt_bf2(pB[i].x, pB[i].y);
            Bh[w + 1] = cvt_bf2(pB[i].z, pB[i].w);
        }
        __syncthreads();
        if (ch < 15) {
            int o = (ch + 1) * 32;
            #pragma unroll
            for (int i = 0; i < 4; i++) {
                pA[i] = *(const float4*)(Ap + (size_t)(i * 16 + r0s) * DIM + o + c0s * 4);
                pB[i] = *(const float4*)(Bp + (size_t)(i * 16 + r0s) * DIM + o + c0s * 4);
            }
        }
        #pragma unroll
        for (int kc = 0; kc < 2; kc++) {
            int cb = kc * 8 + lc;
            unsigned ah[2][4];
            #pragma unroll
            for (int mi = 0; mi < 2; mi++) {
                int r = wm * 32 + mi * 16 + lr;
                ah[mi][0] = Ah[r * LDW + cb];
                ah[mi][1] = Ah[(r + 8) * LDW + cb];
                ah[mi][2] = Ah[r * LDW + cb + 4];
                ah[mi][3] = Ah[(r + 8) * LDW + cb + 4];
            }
            #pragma unroll
            for (int ni = 0; ni < 4; ni++) {
                int n = wn * 32 + ni * 8 + lr;
                unsigned bh[2] = {Bh[n * LDW + cb], Bh[n * LDW + cb + 4]};
                #pragma unroll
                for (int mi = 0; mi < 2; mi++)
                    mma_bf16(acc[mi][ni], ah[mi], bh);
            }
        }
    }

    float* S = g_S + (size_t)q * MM * MM;
    int lc2 = lc * 2;
    #pragma unroll
    for (int mi = 0; mi < 2; mi++) {
        #pragma unroll
        for (int ni = 0; ni < 4; ni++) {
            int r0 = bi * 64 + wm * 32 + mi * 16 + lr;
            int c0 = bj * 64 + wn * 32 + ni * 8 + lc2;
            float* a = acc[mi][ni];
            if (c0 < MM) {
                if (r0 < MM)
                    *(float2*)&S[(size_t)r0 * MM + c0] = make_float2(a[0], a[1]);
                if (r0 + 8 < MM)
                    *(float2*)&S[(size_t)(r0 + 8) * MM + c0] = make_float2(a[2], a[3]);
                if (bi != bj) {
                    if (r0 < MM) {
                        S[(size_t)c0 * MM + r0] = a[0];
                        S[(size_t)(c0 + 1) * MM + r0] = a[1];
                    }
                    if (r0 + 8 < MM) {
                        S[(size_t)c0 * MM + r0 + 8] = a[2];
                        S[(size_t)(c0 + 1) * MM + r0 + 8] = a[3];
                    }
                }
            }
        }
    }
}

// ---- select: approx top-16 candidate indices per row (high occupancy) -------
__global__ __launch_bounds__(256) void select_kernel() {
    int warp = threadIdx.x >> 5, lane = threadIdx.x & 31;
    int row = blockIdx.x * 8 + warp;
    if (row >= NQ * MM) return;
    const float* Srow = g_S + (size_t)row * MM;

    float v[13];
    #pragma unroll
    for (int t = 0; t < 13; t++) {
        int c = lane + t * 32;
        v[t] = (c < MM) ? Srow[c] : -CUDART_INF_F;
    }
    #pragma unroll
    for (int it = 0; it < NCAND; it++) {
        float m = v[0];
        #pragma unroll
        for (int t = 1; t < 13; t++) m = fmaxf(m, v[t]);
        #pragma unroll
        for (int off = 16; off > 0; off >>= 1)
            m = fmaxf(m, __shfl_xor_sync(0xFFFFFFFFu, m, off));
        int c = 0x7FFFFFFF;
        #pragma unroll
        for (int t = 12; t >= 0; t--)
            if (v[t] == m) c = t * 32 + lane;
        #pragma unroll
        for (int off = 16; off > 0; off >>= 1)
            c = min(c, __shfl_xor_sync(0xFFFFFFFFu, c, off));
        if (lane == 0) g_cand[row * NCAND + it] = c;
        #pragma unroll
        for (int t = 0; t < 13; t++)
            if (t * 32 + lane == c) v[t] = -CUDART_INF_F;
    }
}

// ---- exact repair (4-warp-parallel chains) + fused x_dba/res_top ------------
// One 128-thread block per row. All warps stage 16 candidate rows + m-row
// (coalesced). Then warp w runs serial ascending-k fp32 chains for candidates
// 4w..4w+3 (lanes 0..3) -- bitwise == reference S entries -- results to smem.
// Warp 0 extracts top-10 by (value desc, index asc); 128-thread epilogue.
#define CSTRIDE 129   // float4 stride per candidate row (bank-spread)
__global__ __launch_bounds__(128) void exact_kernel(const float* __restrict__ Qm,
                                                    float* __restrict__ out, int full) {
    __shared__ __align__(16) float4 cbuf[NCAND * CSTRIDE];
    __shared__ __align__(16) float4 mbuf[DIM / 4];
    __shared__ int scand[NCAND];
    __shared__ unsigned long long kbuf[NCAND];
    __shared__ int sslot[KTOP];
    __shared__ float ssval[KTOP];
    __shared__ float red[128];
    int m = blockIdx.x, q = blockIdx.y, tid = threadIdx.x;
    int wid = tid >> 5, lane = tid & 31;
    int row = q * MM + m;
    const float* Xq = g_Xs + (size_t)q * MPAD * DIM;

    if (tid < NCAND) scand[tid] = g_cand[row * NCAND + tid];
    mbuf[tid] = ((const float4*)(Xq + (size_t)m * DIM))[tid];
    __syncthreads();
    #pragma unroll
    for (int i = 0; i < NCAND; i++)
        cbuf[i * CSTRIDE + tid] = ((const float4*)(Xq + (size_t)scand[i] * DIM))[tid];
    __syncthreads();

    // chains: warp wid handles candidates 4*wid + 0..3 on lanes 0..3
    {
        bool act = lane < 4;
        int c = wid * 4 + (lane & 3);
        const float4* cp = &cbuf[c * CSTRIDE];
        float acc = 0.0f;
        if (act) {
            #pragma unroll 4
            for (int k4 = 0; k4 < DIM / 4; k4++) {
                float4 rv = mbuf[k4];
                float4 cv = cp[k4];
                acc = __fmaf_rn(rv.x, cv.x, acc);
                acc = __fmaf_rn(rv.y, cv.y, acc);
                acc = __fmaf_rn(rv.z, cv.z, acc);
                acc = __fmaf_rn(rv.w, cv.w, acc);
            }
            kbuf[c] = pack_key(acc, scand[c]);
        }
    }
    __syncthreads();

    // warp 0: top-10 from the 16 packed keys (value desc, index asc)
    if (wid == 0) {
        bool act = lane < NCAND;
        unsigned long long key = act ? kbuf[lane] : 0ULL;
        int ci = act ? scand[lane] : -1;
        #pragma unroll
        for (int it = 0; it < KTOP; it++) {
            unsigned long long best = key;
            #pragma unroll
            for (int off = 16; off > 0; off >>= 1) {
                unsigned long long o = __shfl_xor_sync(0xFFFFFFFFu, best, off);
                if (o > best) best = o;
            }
            int c = (int)(0xFFFFFFFFu - (unsigned int)(best & 0xFFFFFFFFu));
            unsigned bal = __ballot_sync(0xFFFFFFFFu, act && ci == c);
            if (lane == 0) {
                sslot[it] = __ffs(bal) - 1;
                ssval[it] = unordf((unsigned int)(best >> 32));
            }
            if (key == best) key = 0ULL;
        }
    }
    __syncthreads();

    // fused x_dba + res_top (byte-identical math to the proven epilogue)
    float4 a = cbuf[(size_t)sslot[0] * CSTRIDE + tid];   // w0 = 1.0
    float sumw = 1.0f;
    #pragma unroll
    for (int k = 1; k < KTOP; k++) {
        float w = __fmul_rn(BETA, ssval[k]);
        sumw = __fadd_rn(sumw, w);
        float4 v = cbuf[(size_t)sslot[k] * CSTRIDE + tid];
        a.x = __fadd_rn(a.x, __fmul_rn(w, v.x));
        a.y = __fadd_rn(a.y, __fmul_rn(w, v.y));
        a.z = __fadd_rn(a.z, __fmul_rn(w, v.z));
        a.w = __fadd_rn(a.w, __fmul_rn(w, v.w));
    }
    a.x = __fdiv_rn(a.x, sumw);
    a.y = __fdiv_rn(a.y, sumw);
    a.z = __fdiv_rn(a.z, sumw);
    a.w = __fdiv_rn(a.w, sumw);

    if (full)
        *(float4*)(out + OFF_XDBA + (size_t)row * DIM + tid * 4) = a;

    float4 qv = ((const float4*)Qm)[(size_t)q * (DIM / 4) + tid];
    red[tid] = a.x * qv.x + a.y * qv.y + a.z * qv.z + a.w * qv.w;
    __syncthreads();
    #pragma unroll
    for (int s = 64; s > 0; s >>= 1) {
        if (tid < s) red[tid] += red[tid + s];
        __syncthreads();
    }
    if (tid == 0) {
        g_restop[row] = red[0];
        if (full) out[OFF_RESTOP + row] = red[0];
    }
}

// ---- stable descending sort (bitonic 512) + final outputs -------------------
__global__ __launch_bounds__(512) void sort_kernel(float* __restrict__ out,
                                                   int full, int out_size) {
    int q = blockIdx.x, tid = threadIdx.x;
    __shared__ unsigned long long sk[512];
    sk[tid] = (tid < MM) ? pack_key(g_restop[q * MM + tid], tid) : 0ULL;
    __syncthreads();
    for (int k = 2; k <= 512; k <<= 1) {
        for (int j = k >> 1; j > 0; j >>= 1) {
            int ixj = tid ^ j;
            if (ixj > tid) {
                unsigned long long a = sk[tid], b = sk[ixj];
                bool desc = (tid & k) == 0;
                if (desc ? (a < b) : (a > b)) { sk[tid] = b; sk[ixj] = a; }
            }
            __syncthreads();
        }
    }
    if (tid < MM) {
        unsigned int msel = 0xFFFFFFFFu - (unsigned int)(sk[tid] & 0xFFFFFFFFu);
        int o0 = q * MM + tid;
        if (o0 < out_size) out[OFF_RERANK + o0] = (float)g_rt[q * MM + msel];
        if (full) out[OFF_PRE + o0] = (float)msel;
    }
}

extern "C" void kernel_launch(void* const* d_in, const int* in_sizes, int n_in,
                              void* d_out, int out_size) {
    const float* X  = (const float*)d_in[0];
    const float* Qm = (const float*)d_in[1];
    const void*  rk = d_in[2];
    float* out = (float*)d_out;
    int full = (out_size >= FULL_OUT) ? 1 : 0;

    probe_kernel<<<1, 256>>>((const int*)rk);
    gather_kernel<<<dim3(MPAD, NQ), 128>>>(X, rk);
    gemm_kernel<<<dim3(28, NQ), 128>>>();
    select_kernel<<<(NQ * MM + 7) / 8, 256>>>();
    exact_kernel<<<dim3(MM, NQ), 128>>>(Qm, out, full);
    sort_kernel<<<NQ, 512>>>(out, full, out_size);
}

// round 15
// speedup vs baseline: 1.3116x; 1.3116x over previous
#include <cuda_runtime.h>
#include <cstdint>
#include <math_constants.h>

// ---------------------------------------------------------------------------
// MDescAug: per-query candidate reranking with descriptor augmentation.
//   X: [50000,512] f32,  Q: [100,512] f32,  ranks: [50000,100] i32/i64 (probed)
// Output f32 concat: rerank_final[100,400], res_top[100,400], pre[100,400],
//                    x_dba[100,400,512]
// Best-measured-parts build: round-1 serial-k FFMA GEMM (bitwise reference S,
// at the fp32 issue roofline) + round-6 float top-10 + round-1 xdba/sort.
// ---------------------------------------------------------------------------

#define NDB  50000
#define NQ   100
#define DIM  512
#define MM   400
#define KTOP 10
#define BETA 0.15f

#define OFF_RERANK 0
#define OFF_RESTOP 40000
#define OFF_PRE    80000
#define OFF_XDBA   120000
#define FULL_OUT   20600000

// Scratch (device globals; no allocation allowed)
__device__ float g_Xs[(size_t)NQ * MM * DIM];     // gathered descriptors
__device__ float g_S[(size_t)NQ * MM * MM];       // exact similarity
__device__ int   g_rt[NQ * MM];
__device__ int   g_idx[NQ * MM * KTOP];
__device__ float g_vals[NQ * MM * KTOP];
__device__ float g_restop[NQ * MM];
__device__ int   g_is64;

// ---- order-preserving float<->uint ------------------------------------------
__device__ __forceinline__ unsigned int ordf(float f) {
    unsigned int u = __float_as_uint(f);
    return (u & 0x80000000u) ? ~u : (u | 0x80000000u);
}
__device__ __forceinline__ unsigned long long pack_key(float v, int idx) {
    return ((unsigned long long)ordf(v) << 32) |
           (unsigned long long)(0xFFFFFFFFu - (unsigned int)idx);
}

// ---- probe: int64 vs int32 ranks --------------------------------------------
__global__ void probe_kernel(const int* __restrict__ r) {
    __shared__ int cnt;
    if (threadIdx.x == 0) cnt = 0;
    __syncthreads();
    int nz = 0;
    for (int i = threadIdx.x; i < 1024; i += blockDim.x)
        nz += (r[2 * i + 1] != 0);
    atomicAdd(&cnt, nz);
    __syncthreads();
    if (threadIdx.x == 0) g_is64 = (cnt < 100) ? 1 : 0;
}

// ---- gather Xs[q][m][:] = X[ranks[m][q]][:] ---------------------------------
__global__ __launch_bounds__(128) void gather_kernel(const float* __restrict__ X,
                                                     const void* __restrict__ ranks) {
    int m = blockIdx.x, q = blockIdx.y, tid = threadIdx.x;
    int rid;
    if (g_is64) rid = (int)((const long long*)ranks)[(size_t)m * NQ + q];
    else        rid = ((const int*)ranks)[(size_t)m * NQ + q];
    if (tid == 0) g_rt[q * MM + m] = rid;
    const float4* src = (const float4*)(X + (size_t)rid * DIM);
    float4* dst = (float4*)(g_Xs + ((size_t)q * MM + m) * DIM);
    dst[tid] = src[tid];
}

// ---- batched symmetric GEMM: S_q = Xs_q * Xs_q^T (round-1 proven) -----------
// 64x64 tile, BK=16, 256 threads, 4x4 per-thread fragments, serial-k FFMA
// chains (bitwise == reference bracketing). Only bi<=bj tile pairs computed.
__global__ __launch_bounds__(256) void gemm_kernel() {
    int p = blockIdx.x, q = blockIdx.y;
    int bi = 0, bj = 0;
    {
        int t = 0;
        #pragma unroll
        for (int i = 0; i < 7; i++) {
            int c = 7 - i;
            if (p < t + c) { bi = i; bj = i + (p - t); break; }
            t += c;
        }
    }
    const float* A = g_Xs + (size_t)q * MM * DIM;
    float* S = g_S + (size_t)q * MM * MM;

    __shared__ __align__(16) float As[16][68];
    __shared__ __align__(16) float Bs[16][68];

    int tid = threadIdx.x;
    int tx = tid & 15, ty = tid >> 4;
    int lrow = tid >> 2;   // 0..63
    int lseg = tid & 3;    // 0..3
    int arow = bi * 64 + lrow;
    int brow = bj * 64 + lrow;

    float acc[4][4];
    #pragma unroll
    for (int r = 0; r < 4; r++)
        #pragma unroll
        for (int c = 0; c < 4; c++) acc[r][c] = 0.0f;

    const float4 z4 = make_float4(0.f, 0.f, 0.f, 0.f);

    for (int kt = 0; kt < DIM; kt += 16) {
        float4 av = (arow < MM) ? *(const float4*)(A + (size_t)arow * DIM + kt + lseg * 4) : z4;
        float4 bv = (brow < MM) ? *(const float4*)(A + (size_t)brow * DIM + kt + lseg * 4) : z4;
        As[lseg * 4 + 0][lrow] = av.x;
        As[lseg * 4 + 1][lrow] = av.y;
        As[lseg * 4 + 2][lrow] = av.z;
        As[lseg * 4 + 3][lrow] = av.w;
        Bs[lseg * 4 + 0][lrow] = bv.x;
        Bs[lseg * 4 + 1][lrow] = bv.y;
        Bs[lseg * 4 + 2][lrow] = bv.z;
        Bs[lseg * 4 + 3][lrow] = bv.w;
        __syncthreads();
        #pragma unroll
        for (int kk = 0; kk < 16; kk++) {
            float4 a4 = *(const float4*)&As[kk][ty * 4];
            float4 b4 = *(const float4*)&Bs[kk][tx * 4];
            float ar[4] = {a4.x, a4.y, a4.z, a4.w};
            float br[4] = {b4.x, b4.y, b4.z, b4.w};
            #pragma unroll
            for (int r = 0; r < 4; r++)
                #pragma unroll
                for (int c = 0; c < 4; c++)
                    acc[r][c] += ar[r] * br[c];
        }
        __syncthreads();
    }

    int ro = bi * 64 + ty * 4;
    int co = bj * 64 + tx * 4;

    #pragma unroll
    for (int r = 0; r < 4; r++) {
        int row = ro + r;
        if (row < MM) {
            if (co + 4 <= MM) {
                float4 v = make_float4(acc[r][0], acc[r][1], acc[r][2], acc[r][3]);
                *(float4*)(S + (size_t)row * MM + co) = v;
            } else {
                #pragma unroll
                for (int c = 0; c < 4; c++)
                    if (co + c < MM) S[(size_t)row * MM + co + c] = acc[r][c];
            }
        }
    }
    if (bi != bj) {
        #pragma unroll
        for (int c = 0; c < 4; c++) {
            int col = co + c;
            if (col < MM) {
                float4 v = make_float4(acc[0][c], acc[1][c], acc[2][c], acc[3][c]);
                *(float4*)(S + (size_t)col * MM + ro) = v;
            }
        }
    }
}

// ---- top-10 per row (round-6 proven float version) --------------------------
__global__ __launch_bounds__(256) void topk_kernel() {
    int warp = threadIdx.x >> 5, lane = threadIdx.x & 31;
    int row = blockIdx.x * 8 + warp;
    if (row >= NQ * MM) return;
    const float* Srow = g_S + (size_t)row * MM;

    float v[13];
    #pragma unroll
    for (int t = 0; t < 13; t++) {
        int c = lane + t * 32;
        v[t] = (c < MM) ? Srow[c] : -CUDART_INF_F;
    }
    #pragma unroll
    for (int it = 0; it < KTOP; it++) {
        float m = v[0];
        #pragma unroll
        for (int t = 1; t < 13; t++) m = fmaxf(m, v[t]);
        #pragma unroll
        for (int off = 16; off > 0; off >>= 1)
            m = fmaxf(m, __shfl_xor_sync(0xFFFFFFFFu, m, off));
        int c = 0x7FFFFFFF;
        #pragma unroll
        for (int t = 12; t >= 0; t--)
            if (v[t] == m) c = t * 32 + lane;
        #pragma unroll
        for (int off = 16; off > 0; off >>= 1)
            c = min(c, __shfl_xor_sync(0xFFFFFFFFu, c, off));
        if (lane == 0) {
            g_idx[row * KTOP + it] = c;
            g_vals[row * KTOP + it] = m;
        }
        #pragma unroll
        for (int t = 0; t < 13; t++)
            if (t * 32 + lane == c) v[t] = -CUDART_INF_F;
    }
}

// ---- x_dba + res_top (round-1 proven) ---------------------------------------
__global__ __launch_bounds__(128) void xdba_kernel(const float* __restrict__ Qm,
                                                   float* __restrict__ out, int full) {
    int m = blockIdx.x, q = blockIdx.y, tid = threadIdx.x;
    int row = q * MM + m;
    __shared__ int sidx[KTOP];
    __shared__ float sval[KTOP];
    __shared__ float red[128];
    if (tid < KTOP) {
        sidx[tid] = g_idx[row * KTOP + tid];
        sval[tid] = g_vals[row * KTOP + tid];
    }
    __syncthreads();

    const float4* Xq = (const float4*)(g_Xs + (size_t)q * MM * DIM);
    float4 a = Xq[(size_t)sidx[0] * (DIM / 4) + tid];  // w0 = 1.0
    float sumw = 1.0f;
    #pragma unroll
    for (int k = 1; k < KTOP; k++) {
        float w = __fmul_rn(BETA, sval[k]);
        sumw = __fadd_rn(sumw, w);
        float4 v = Xq[(size_t)sidx[k] * (DIM / 4) + tid];
        a.x = __fadd_rn(a.x, __fmul_rn(w, v.x));
        a.y = __fadd_rn(a.y, __fmul_rn(w, v.y));
        a.z = __fadd_rn(a.z, __fmul_rn(w, v.z));
        a.w = __fadd_rn(a.w, __fmul_rn(w, v.w));
    }
    a.x = __fdiv_rn(a.x, sumw);
    a.y = __fdiv_rn(a.y, sumw);
    a.z = __fdiv_rn(a.z, sumw);
    a.w = __fdiv_rn(a.w, sumw);

    if (full)
        *(float4*)(out + OFF_XDBA + (size_t)row * DIM + tid * 4) = a;

    float4 qv = ((const float4*)Qm)[(size_t)q * (DIM / 4) + tid];
    red[tid] = a.x * qv.x + a.y * qv.y + a.z * qv.z + a.w * qv.w;
    __syncthreads();
    #pragma unroll
    for (int s = 64; s > 0; s >>= 1) {
        if (tid < s) red[tid] += red[tid + s];
        __syncthreads();
    }
    if (tid == 0) {
        g_restop[row] = red[0];
        if (full) out[OFF_RESTOP + row] = red[0];
    }
}

// ---- stable descending sort (bitonic 512) + final outputs -------------------
__global__ __launch_bounds__(512) void sort_kernel(float* __restrict__ out,
                                                   int full, int out_size) {
    int q = blockIdx.x, tid = threadIdx.x;
    __shared__ unsigned long long sk[512];
    sk[tid] = (tid < MM) ? pack_key(g_restop[q * MM + tid], tid) : 0ULL;
    __syncthreads();
    for (int k = 2; k <= 512; k <<= 1) {
        for (int j = k >> 1; j > 0; j >>= 1) {
            int ixj = tid ^ j;
            if (ixj > tid) {
                unsigned long long a = sk[tid], b = sk[ixj];
                bool desc = (tid & k) == 0;
                if (desc ? (a < b) : (a > b)) { sk[tid] = b; sk[ixj] = a; }
            }
            __syncthreads();
        }
    }
    if (tid < MM) {
        unsigned int msel = 0xFFFFFFFFu - (unsigned int)(sk[tid] & 0xFFFFFFFFu);
        int o0 = q * MM + tid;
        if (o0 < out_size) out[OFF_RERANK + o0] = (float)g_rt[q * MM + msel];
        if (full) out[OFF_PRE + o0] = (float)msel;
    }
}

extern "C" void kernel_launch(void* const* d_in, const int* in_sizes, int n_in,
                              void* d_out, int out_size) {
    const float* X  = (const float*)d_in[0];
    const float* Qm = (const float*)d_in[1];
    const void*  rk = d_in[2];
    float* out = (float*)d_out;
    int full = (out_size >= FULL_OUT) ? 1 : 0;

    probe_kernel<<<1, 256>>>((const int*)rk);
    gather_kernel<<<dim3(MM, NQ), 128>>>(X, rk);
    gemm_kernel<<<dim3(28, NQ), 256>>>();
    topk_kernel<<<(NQ * MM + 7) / 8, 256>>>();
    xdba_kernel<<<dim3(MM, NQ), 128>>>(Qm, out, full);
    sort_kernel<<<NQ, 512>>>(out, full, out_size);
}